// round 14
// baseline (speedup 1.0000x reference)
#include <cuda_runtime.h>
#include <cuda_fp16.h>
#include <math.h>
#include <stdint.h>

// ---------------- problem constants ----------------
#define B_   8
#define E_   8
#define C_   128
#define KW_  512
#define Mtot 16384          // B*L
#define KKd  4096           // KW*E
#define NNd  256            // 2*C

// ---------------- GEMM tiling ----------------
#define MT     64           // CTA M tile
#define NTC    128          // CTA N tile (half the channels, W1|W2 paired)
#define KC     64           // K chunk (fp16 elems)
#define NCHUNK (KKd / KC)   // 64
#define NTH    128          // 4 warps: 2(M) x 2(N), warp tile 32x64
#define NCTA   (2 * Mtot / MT)  // 512 (m-tiles x 2 n-halves)

// smem (bytes)
#define PITCH   144         // 64 fp16 data + 8 pad -> conflict-free ldmatrix
#define A_STG   (64 * PITCH)          // 9216 per stage
#define B_STG   (NTC * PITCH)         // 18432 per stage
#define SM_A    0
#define SM_B    (2 * A_STG)           // 18432
#define SMEMSZ  (SM_B + 2 * B_STG)    // 55296 -> 4 CTAs = 221KB/SM
#define VPITCH  68                    // epilogue overlay [64][68] f32 = 17408B

// fp16 weights, [n][kk] K-major, channel-paired layout:
//   n = (c>>6)*128 + (c&63)        -> W1 channel c
//   n = (c>>6)*128 + 64 + (c&63)   -> W2 channel c
__device__ __half g_Bh[(size_t)NNd * KKd];

// ---------------- helpers ----------------
__device__ __forceinline__ uint32_t smem_u32(const void* p) {
    uint32_t a;
    asm("{ .reg .u64 t; cvta.to.shared.u64 t, %1; cvt.u32.u64 %0, t; }" : "=r"(a) : "l"(p));
    return a;
}
__device__ __forceinline__ uint32_t pack_h2(float x, float y) {
    __half2 t = __floats2half2_rn(x, y);
    return *reinterpret_cast<uint32_t*>(&t);
}
__device__ __forceinline__ void ldmx4(uint32_t* r, uint32_t addr) {
    asm volatile("ldmatrix.sync.aligned.m8n8.x4.shared.b16 {%0,%1,%2,%3}, [%4];"
                 : "=r"(r[0]), "=r"(r[1]), "=r"(r[2]), "=r"(r[3]) : "r"(addr));
}
__device__ __forceinline__ void mma16816(float* d, const uint32_t* a, uint32_t b0, uint32_t b1) {
    asm volatile("mma.sync.aligned.m16n8k16.row.col.f32.f16.f16.f32 "
                 "{%0,%1,%2,%3}, {%4,%5,%6,%7}, {%8,%9}, {%0,%1,%2,%3};"
                 : "+f"(d[0]), "+f"(d[1]), "+f"(d[2]), "+f"(d[3])
                 : "r"(a[0]), "r"(a[1]), "r"(a[2]), "r"(a[3]), "r"(b0), "r"(b1));
}
__device__ __forceinline__ void sts128(uint32_t a, uint32_t x, uint32_t y, uint32_t z, uint32_t w) {
    asm volatile("st.shared.v4.b32 [%0], {%1,%2,%3,%4};"
                 :: "r"(a), "r"(x), "r"(y), "r"(z), "r"(w) : "memory");
}
__device__ __forceinline__ void stsf2(uint32_t a, float x, float y) {
    asm volatile("st.shared.v2.f32 [%0], {%1,%2};" :: "r"(a), "f"(x), "f"(y) : "memory");
}
__device__ __forceinline__ void cpasync16(uint32_t dst, const void* src) {
    asm volatile("cp.async.cg.shared.global [%0], [%1], 16;" :: "r"(dst), "l"(src) : "memory");
}
__device__ __forceinline__ void cp_commit() { asm volatile("cp.async.commit_group;" ::: "memory"); }
__device__ __forceinline__ void cp_wait1() { asm volatile("cp.async.wait_group 1;" ::: "memory"); }
__device__ __forceinline__ void cp_wait0() { asm volatile("cp.async.wait_group 0;" ::: "memory"); }
__device__ __forceinline__ void atomicMaxFloat(float* addr, float val) {
    if (val >= 0.0f) atomicMax((int*)addr, __float_as_int(val));
    else             atomicMin((unsigned int*)addr, __float_as_uint(val));
}

// ---------------- prep: weights -> fp16 paired layout; also init out ----------------
__global__ void prep_weights(const float* __restrict__ W1, const float* __restrict__ W2,
                             float* __restrict__ out) {
    int idx = blockIdx.x * blockDim.x + threadIdx.x;   // over C_*KW_ = 65536
    if (idx < B_ * C_) out[idx] = -INFINITY;
    if (idx >= C_ * KW_) return;
    int c = idx / KW_;
    int k = idx % KW_;
    uint32_t p1[4], p2[4];
#pragma unroll
    for (int e2 = 0; e2 < 4; e2++) {
        float a0 = W1[((size_t)c * E_ + 2 * e2) * KW_ + k];
        float a1 = W1[((size_t)c * E_ + 2 * e2 + 1) * KW_ + k];
        p1[e2] = pack_h2(a0, a1);
        float b0 = W2[((size_t)c * E_ + 2 * e2) * KW_ + k];
        float b1v = W2[((size_t)c * E_ + 2 * e2 + 1) * KW_ + k];
        p2[e2] = pack_h2(b0, b1v);
    }
    int n1 = (c >> 6) * 128 + (c & 63);
    int n2 = n1 + 64;
    *(uint4*)&g_Bh[(size_t)n1 * KKd + k * E_] = make_uint4(p1[0], p1[1], p1[2], p1[3]);
    *(uint4*)&g_Bh[(size_t)n2 * KKd + k * E_] = make_uint4(p2[0], p2[1], p2[2], p2[3]);
}

// ---------------- main fused GEMM + gate + max ----------------
__global__ __launch_bounds__(NTH, 4)
void gemm_gate_max(const float* __restrict__ Z,
                   const float* __restrict__ b1,
                   const float* __restrict__ b2,
                   float* __restrict__ out) {
    extern __shared__ char smem[];
    const uint32_t sb = smem_u32(smem);
    const int tid  = threadIdx.x;
    const int wid  = tid >> 5;
    const int lane = tid & 31;
    const int wm   = wid & 1;        // M group (0..1), 32 rows each
    const int wn   = wid >> 1;       // N group (0..1), 64 cols each
    const int mtile = blockIdx.x >> 1;
    const int nhalf = blockIdx.x & 1;   // adjacent CTAs share the A tile (L2 reuse)
    const int m_base = mtile * MT;
    const int n_base = nhalf * NTC;

    const uint32_t fragBase = (uint32_t)((lane % 16) * PITCH + (lane / 16) * 16);
    const uint32_t wmOff = (uint32_t)(wm * 32 * PITCH);
    const uint32_t wnOff = (uint32_t)(wn * 64 * PITCH);

    // ---- A staging: 4 granules (8 floats -> 16B fp16) per thread per chunk ----
    const int r0 = tid >> 3;           // 0..15
    const int u  = tid & 7;            // granule in row (8 fp16 = 16B each)
    const float* aSrc0 = Z + (size_t)(m_base + r0) * KKd + u * 8;       // +q*16 rows
    const uint32_t aDst0 = (uint32_t)(r0 * PITCH + u * 16);             // +q*16*PITCH
    // ---- B staging: 8 granules (16B) per thread per chunk (128 rows) ----
    const __half* bSrc0 = g_Bh + (size_t)(n_base + r0) * KKd + u * 8;   // +q*16 rows
    const uint32_t bDst0 = aDst0;

    float acc[2][8][4];
#pragma unroll
    for (int mi = 0; mi < 2; mi++)
#pragma unroll
        for (int ni = 0; ni < 8; ni++)
#pragma unroll
            for (int q = 0; q < 4; q++) acc[mi][ni][q] = 0.0f;

    uint32_t pA[16];   // packed fp16 A prefetch: 4 granules x 4 regs

    // ---- prologue: chunk 0 ----
#pragma unroll
    for (int q = 0; q < 8; q++)
        cpasync16(sb + SM_B + bDst0 + q * (16 * PITCH), bSrc0 + (size_t)q * 16 * KKd);
    cp_commit();
#pragma unroll
    for (int q = 0; q < 4; q++) {
        float4 v0 = *(const float4*)(aSrc0 + (size_t)q * 16 * KKd);
        float4 v1 = *(const float4*)(aSrc0 + (size_t)q * 16 * KKd + 4);
        sts128(sb + SM_A + aDst0 + q * (16 * PITCH),
               pack_h2(v0.x, v0.y), pack_h2(v0.z, v0.w),
               pack_h2(v1.x, v1.y), pack_h2(v1.z, v1.w));
    }
#pragma unroll
    for (int q = 0; q < 4; q++) {
        float4 v0 = *(const float4*)(aSrc0 + (size_t)q * 16 * KKd + KC);
        float4 v1 = *(const float4*)(aSrc0 + (size_t)q * 16 * KKd + KC + 4);
        pA[4 * q]     = pack_h2(v0.x, v0.y);
        pA[4 * q + 1] = pack_h2(v0.z, v0.w);
        pA[4 * q + 2] = pack_h2(v1.x, v1.y);
        pA[4 * q + 3] = pack_h2(v1.z, v1.w);
    }

    for (int j = 0; j < NCHUNK; ++j) {
        const uint32_t cur = j & 1;
        const uint32_t nxt = cur ^ 1;

        __syncthreads();   // chunk j-1 consumed -> safe to overwrite stage nxt

        if (j + 1 < NCHUNK) {
            const int ke = (j + 1) * KC;
#pragma unroll
            for (int q = 0; q < 8; q++)
                cpasync16(sb + SM_B + nxt * B_STG + bDst0 + q * (16 * PITCH),
                          bSrc0 + (size_t)q * 16 * KKd + ke);
            cp_commit();
#pragma unroll
            for (int q = 0; q < 4; q++)
                sts128(sb + SM_A + nxt * A_STG + aDst0 + q * (16 * PITCH),
                       pA[4 * q], pA[4 * q + 1], pA[4 * q + 2], pA[4 * q + 3]);
            cp_wait1();
        } else {
            cp_wait0();
        }
        __syncthreads();   // stage cur fully visible

        if (j + 2 < NCHUNK) {
#pragma unroll
            for (int q = 0; q < 4; q++) {
                float4 v0 = *(const float4*)(aSrc0 + (size_t)q * 16 * KKd + (j + 2) * KC);
                float4 v1 = *(const float4*)(aSrc0 + (size_t)q * 16 * KKd + (j + 2) * KC + 4);
                pA[4 * q]     = pack_h2(v0.x, v0.y);
                pA[4 * q + 1] = pack_h2(v0.z, v0.w);
                pA[4 * q + 2] = pack_h2(v1.x, v1.y);
                pA[4 * q + 3] = pack_h2(v1.z, v1.w);
            }
        }

        // ---- compute chunk j: 4 k16 slices ----
        const uint32_t sA = sb + SM_A + cur * A_STG;
        const uint32_t sB = sb + SM_B + cur * B_STG;

#pragma unroll
        for (int ks = 0; ks < 4; ks++) {
            const uint32_t ko = (uint32_t)(ks * 32);
            uint32_t af[2][4], bf[4][4];
#pragma unroll
            for (int mi = 0; mi < 2; mi++)
                ldmx4(af[mi], sA + wmOff + mi * (16 * PITCH) + ko + fragBase);
#pragma unroll
            for (int n2 = 0; n2 < 4; n2++)
                ldmx4(bf[n2], sB + wnOff + n2 * (16 * PITCH) + ko + fragBase);
#pragma unroll
            for (int mi = 0; mi < 2; mi++)
#pragma unroll
                for (int ni = 0; ni < 8; ni++)
                    mma16816(acc[mi][ni], af[mi], bf[ni >> 1][(ni & 1)], bf[ni >> 1][(ni & 1) + 2]);
        }
    }

    // ---- epilogue ----
    __syncthreads();   // pipe done; reuse smem as v2 tile [64][VPITCH] floats

    const int laneR = lane >> 2;
    const int laneC = (lane & 3) * 2;

    if (wn == 1) {
        // dump v2 half (local cols 64..127 -> tile cols 0..63)
#pragma unroll
        for (int mi = 0; mi < 2; mi++) {
#pragma unroll
            for (int ni = 0; ni < 8; ni++) {
                int r = wm * 32 + mi * 16 + laneR;
                int c = ni * 8 + laneC;
                uint32_t a0 = sb + (uint32_t)(r * (VPITCH * 4) + c * 4);
                stsf2(a0,                    acc[mi][ni][0], acc[mi][ni][1]);
                stsf2(a0 + 8 * (VPITCH * 4), acc[mi][ni][2], acc[mi][ni][3]);
            }
        }
    }
    __syncthreads();

    if (wn == 0) {
        const float* sV = (const float*)smem;
        const int bidx = mtile >> 5;   // 32 m-tiles per batch
        float gm[8][2];
#pragma unroll
        for (int ni = 0; ni < 8; ni++) {
            const int cl = ni * 8 + laneC;            // local channel 0..63
            const int c  = n_base ? 64 + cl : cl;     // global channel
            const float bb1a = __ldg(&b1[c]),     bb1b = __ldg(&b1[c + 1]);
            const float bb2a = __ldg(&b2[c]),     bb2b = __ldg(&b2[c + 1]);
            float m0 = -INFINITY, m1 = -INFINITY;
#pragma unroll
            for (int mi = 0; mi < 2; mi++) {
                int r0r = wm * 32 + mi * 16 + laneR;
                float v2a0 = sV[r0r * VPITCH + cl]           + bb2a;
                float v2b0 = sV[r0r * VPITCH + cl + 1]       + bb2b;
                float v2a1 = sV[(r0r + 8) * VPITCH + cl]     + bb2a;
                float v2b1 = sV[(r0r + 8) * VPITCH + cl + 1] + bb2b;
                float g0 = (acc[mi][ni][0] + bb1a) / (1.0f + __expf(-v2a0));
                float g1 = (acc[mi][ni][1] + bb1b) / (1.0f + __expf(-v2b0));
                float g2 = (acc[mi][ni][2] + bb1a) / (1.0f + __expf(-v2a1));
                float g3 = (acc[mi][ni][3] + bb1b) / (1.0f + __expf(-v2b1));
                m0 = fmaxf(m0, fmaxf(g0, g2));
                m1 = fmaxf(m1, fmaxf(g1, g3));
            }
            gm[ni][0] = m0;
            gm[ni][1] = m1;
        }
#pragma unroll
        for (int ni = 0; ni < 8; ni++) {
#pragma unroll
            for (int off = 4; off < 32; off <<= 1) {
                gm[ni][0] = fmaxf(gm[ni][0], __shfl_xor_sync(0xffffffffu, gm[ni][0], off));
                gm[ni][1] = fmaxf(gm[ni][1], __shfl_xor_sync(0xffffffffu, gm[ni][1], off));
            }
        }
        if (laneR == 0) {
#pragma unroll
            for (int ni = 0; ni < 8; ni++) {
                const int cl = ni * 8 + laneC;
                const int c  = n_base ? 64 + cl : cl;
                atomicMaxFloat(&out[bidx * C_ + c],     gm[ni][0]);
                atomicMaxFloat(&out[bidx * C_ + c + 1], gm[ni][1]);
            }
        }
    }
}

extern "C" void kernel_launch(void* const* d_in, const int* in_sizes, int n_in,
                              void* d_out, int out_size) {
    const float* z  = (const float*)d_in[0];
    const float* W1 = (const float*)d_in[1];
    const float* b1 = (const float*)d_in[2];
    const float* W2 = (const float*)d_in[3];
    const float* b2 = (const float*)d_in[4];
    float* out = (float*)d_out;
    (void)in_sizes; (void)n_in; (void)out_size;

    cudaFuncSetAttribute(gemm_gate_max, cudaFuncAttributeMaxDynamicSharedMemorySize, SMEMSZ);

    prep_weights<<<(C_ * KW_ + 255) / 256, 256>>>(W1, W2, out);
    gemm_gate_max<<<NCTA, NTH, SMEMSZ>>>(z, b1, b2, out);
}